// round 1
// baseline (speedup 1.0000x reference)
#include <cuda_runtime.h>
#include <math.h>

#define NGRID 128
#define NG3 (NGRID*NGRID*NGRID)
#define CCH 32
#define RAD 8          // conv kernel radius; k(8)/k(0) ~ 1e-14
#define MAXN 32768

// Scratch (static device allocations are allowed; cudaMalloc is not)
__device__ float g_field0[NG3];   // 8 MB
__device__ float g_field1[NG3];   // 8 MB
__device__ float g_s[MAXN];       // per-particle channel-summed feature
__device__ float g_taps[RAD+1];   // exact real-space taps of the spectral filter

// ---------------------------------------------------------------------------
// taps: k(d) = (1/128) [ g(0) + 2*sum_{m=1..63} g(m) cos(pi m d / 64)
//                        + g(64) cos(pi d) ],  g(m) = exp(-0.5*(pi m/64)^2)
// This is the EXACT inverse DFT of exp(-0.5*sig^2*k^2) with sig = h = L/NG.
// ---------------------------------------------------------------------------
__global__ void k_taps() {
    int d = threadIdx.x;
    if (d <= RAD) {
        double acc = 1.0;  // m = 0 term
        for (int m = 1; m < 64; m++) {
            double a = M_PI * (double)m / 64.0;
            acc += 2.0 * exp(-0.5 * a * a) * cos(M_PI * (double)(m * d) / 64.0);
        }
        acc += exp(-0.5 * M_PI * M_PI) * cos(M_PI * (double)d);  // m = 64 (Nyquist)
        g_taps[d] = (float)(acc / 128.0);
    }
}

__global__ void k_zero() {
    int i = blockIdx.x * blockDim.x + threadIdx.x;
    reinterpret_cast<float4*>(g_field0)[i] = make_float4(0.f, 0.f, 0.f, 0.f);
}

// ---------------------------------------------------------------------------
// MLP: x = emb[z]; x = silu(x@W0^T+b0); x = silu(x@W1^T+b1); s = sum_c x
// One thread per particle; emb/W0/W1 staged in smem.
// ---------------------------------------------------------------------------
__global__ void k_mlp(const int* __restrict__ z, const float* __restrict__ emb,
                      const float* __restrict__ W0, const float* __restrict__ b0,
                      const float* __restrict__ W1, const float* __restrict__ b1,
                      int n) {
    __shared__ float sEmb[128 * CCH];
    __shared__ float sW0[CCH * CCH];
    __shared__ float sW1[CCH * CCH];
    __shared__ float sb0[CCH], sb1[CCH];
    for (int i = threadIdx.x; i < 128 * CCH; i += blockDim.x) sEmb[i] = emb[i];
    for (int i = threadIdx.x; i < CCH * CCH; i += blockDim.x) { sW0[i] = W0[i]; sW1[i] = W1[i]; }
    if (threadIdx.x < CCH) { sb0[threadIdx.x] = b0[threadIdx.x]; sb1[threadIdx.x] = b1[threadIdx.x]; }
    __syncthreads();

    int i = blockIdx.x * blockDim.x + threadIdx.x;
    if (i >= n) return;
    int zi = z[i];
    float x[CCH], y[CCH];
    #pragma unroll
    for (int c = 0; c < CCH; c++) x[c] = sEmb[zi * CCH + c];
    #pragma unroll
    for (int r = 0; r < CCH; r++) {
        float a = sb0[r];
        #pragma unroll
        for (int c = 0; c < CCH; c++) a += sW0[r * CCH + c] * x[c];
        y[r] = a / (1.f + __expf(-a));               // silu
    }
    float s = 0.f;
    #pragma unroll
    for (int r = 0; r < CCH; r++) {
        float a = sb1[r];
        #pragma unroll
        for (int c = 0; c < CCH; c++) a += sW1[r * CCH + c] * y[c];
        s += a / (1.f + __expf(-a));                 // silu, then channel-sum
    }
    g_s[i] = s;
}

// ---------------------------------------------------------------------------
// Window helper: offsets = {-1,0,1,2} per axis (P=4, arange(P) - (P//2-1))
// ---------------------------------------------------------------------------
__device__ __forceinline__ void window_cell(const float* __restrict__ pos, int i, int t,
                                            float& w, int& idx) {
    const float h = 10.0f / 128.0f;     // exact in fp32
    const float inv = 1.0f / h;
    int a = t >> 4, b = (t >> 2) & 3, c = t & 3;   // x-, y-, z-offset indices
    float px = fmodf(pos[3 * i + 0], 10.0f);
    float py = fmodf(pos[3 * i + 1], 10.0f);
    float pz = fmodf(pos[3 * i + 2], 10.0f);
    int cx = (int)floorf(px / h) + a - 1;
    int cy = (int)floorf(py / h) + b - 1;
    int cz = (int)floorf(pz / h) + c - 1;
    float dx = (px - (float)cx * h) * inv;
    float dy = (py - (float)cy * h) * inv;
    float dz = (pz - (float)cz * h) * inv;
    w = __expf(-0.5f * (dx * dx + dy * dy + dz * dz));
    idx = (((cz & 127) * 128 + (cy & 127)) * 128 + (cx & 127));
}

// 64 threads per particle, 4 particles per 256-thread block
__global__ void k_scatter(const float* __restrict__ pos, int n) {
    int lp = threadIdx.x >> 6;
    int t  = threadIdx.x & 63;
    int i = blockIdx.x * 4 + lp;
    if (i >= n) return;
    float w; int idx;
    window_cell(pos, i, t, w, idx);
    atomicAdd(&g_field0[idx], w * g_s[i]);
}

__global__ void k_gather(const float* __restrict__ pos, float* __restrict__ out, int n) {
    __shared__ float part[8];
    int lp = threadIdx.x >> 6;
    int t  = threadIdx.x & 63;
    int i = blockIdx.x * 4 + lp;
    float v = 0.f;
    if (i < n) {
        float w; int idx;
        window_cell(pos, i, t, w, idx);
        v = w * g_field1[idx];
    }
    #pragma unroll
    for (int o = 16; o; o >>= 1) v += __shfl_xor_sync(0xffffffffu, v, o);
    if ((threadIdx.x & 31) == 0) part[threadIdx.x >> 5] = v;
    __syncthreads();
    if (t == 0 && i < n) out[i] = part[2 * lp] + part[2 * lp + 1];
}

// ---------------------------------------------------------------------------
// Separable circular conv along z or y. Block: 32-wide x-chunk (contiguous),
// full 128 along the conv axis, fixed "other" coord. 16 KB smem tile.
//   z-pass: astride = 128*128, ostride = 128,        dir=0: field0 -> field1
//   y-pass: astride = 128,     ostride = 128*128,    dir=1: field1 -> field0
// ---------------------------------------------------------------------------
__global__ void k_conv(int astride, int ostride, int dir) {
    const float* __restrict__ in = dir ? g_field1 : g_field0;
    float* __restrict__ out      = dir ? g_field0 : g_field1;
    __shared__ float tile[NGRID][32];
    float tp[RAD + 1];
    #pragma unroll
    for (int d = 0; d <= RAD; d++) tp[d] = g_taps[d];
    int tx = threadIdx.x & 31;
    int tz = threadIdx.x >> 5;            // 0..7
    int x0 = blockIdx.x * 32;
    int other = blockIdx.y;
    const float* base = in + other * ostride + x0 + tx;
    #pragma unroll
    for (int zz = tz; zz < NGRID; zz += 8)
        tile[zz][tx] = base[zz * astride];
    __syncthreads();
    float* ob = out + other * ostride + x0 + tx;
    #pragma unroll
    for (int zz = tz; zz < NGRID; zz += 8) {
        float acc = tp[0] * tile[zz][tx];
        #pragma unroll
        for (int d = 1; d <= RAD; d++)
            acc += tp[d] * (tile[(zz + d) & 127][tx] + tile[(zz - d) & 127][tx]);
        ob[zz * astride] = acc;
    }
}

// x-axis pass (lines are contiguous). 8 lines per 256-thread block. field0->field1.
__global__ void k_conv_x() {
    __shared__ float tile[8][NGRID];
    float tp[RAD + 1];
    #pragma unroll
    for (int d = 0; d <= RAD; d++) tp[d] = g_taps[d];
    int lx = threadIdx.x & 31;
    int ln = threadIdx.x >> 5;            // 0..7
    int line = blockIdx.x * 8 + ln;
    const float* base = g_field0 + line * NGRID;
    #pragma unroll
    for (int k = 0; k < 4; k++) tile[ln][lx + 32 * k] = base[lx + 32 * k];
    __syncthreads();
    float* ob = g_field1 + line * NGRID;
    #pragma unroll
    for (int k = 0; k < 4; k++) {
        int xx = lx + 32 * k;
        float acc = tp[0] * tile[ln][xx];
        #pragma unroll
        for (int d = 1; d <= RAD; d++)
            acc += tp[d] * (tile[ln][(xx + d) & 127] + tile[ln][(xx - d) & 127]);
        ob[xx] = acc;
    }
}

extern "C" void kernel_launch(void* const* d_in, const int* in_sizes, int n_in,
                              void* d_out, int out_size) {
    const int*   z   = (const int*)  d_in[0];
    const float* pos = (const float*)d_in[1];
    // d_in[2] = batch (all zeros, NBATCH=1) — unused
    const float* emb = (const float*)d_in[3];
    const float* W0  = (const float*)d_in[4];
    const float* b0  = (const float*)d_in[5];
    const float* W1  = (const float*)d_in[6];
    const float* b1  = (const float*)d_in[7];
    float* out = (float*)d_out;
    int n = in_sizes[0];

    k_taps<<<1, 32>>>();
    k_zero<<<NG3 / 4 / 256, 256>>>();
    k_mlp<<<(n + 127) / 128, 128>>>(z, emb, W0, b0, W1, b1, n);
    k_scatter<<<(n + 3) / 4, 256>>>(pos, n);
    k_conv<<<dim3(4, 128), 256>>>(NGRID * NGRID, NGRID, 0);  // z-axis: f0 -> f1
    k_conv<<<dim3(4, 128), 256>>>(NGRID, NGRID * NGRID, 1);  // y-axis: f1 -> f0
    k_conv_x<<<NGRID * NGRID / 8, 256>>>();                  // x-axis: f0 -> f1
    k_gather<<<(n + 3) / 4, 256>>>(pos, out, n);
}

// round 2
// speedup vs baseline: 3.0496x; 3.0496x over previous
#include <cuda_runtime.h>
#include <math.h>

#define NGRID 128
#define NG3 (NGRID*NGRID*NGRID)
#define CCH 32
#define RAD 8          // conv kernel radius; k(8)/k(0) ~ 1e-14
#define MAXN 32768

// Scratch (static device allocations are allowed; cudaMalloc is not)
__device__ float g_field0[NG3];   // 8 MB
__device__ float g_field1[NG3];   // 8 MB
__device__ float g_s[MAXN];       // per-particle channel-summed feature

// Taps passed by value (computed on host, baked into the graph)
struct Taps { float t[RAD + 1]; };

__global__ void k_zero() {
    int i = blockIdx.x * blockDim.x + threadIdx.x;
    reinterpret_cast<float4*>(g_field0)[i] = make_float4(0.f, 0.f, 0.f, 0.f);
}

// ---------------------------------------------------------------------------
// MLP: x = emb[z]; x = silu(x@W0^T+b0); x = silu(x@W1^T+b1); s = sum_c x
// One thread per particle; emb/W0/W1 staged in smem.
// ---------------------------------------------------------------------------
__global__ void k_mlp(const int* __restrict__ z, const float* __restrict__ emb,
                      const float* __restrict__ W0, const float* __restrict__ b0,
                      const float* __restrict__ W1, const float* __restrict__ b1,
                      int n) {
    __shared__ float sEmb[128 * CCH];
    __shared__ float sW0[CCH * CCH];
    __shared__ float sW1[CCH * CCH];
    __shared__ float sb0[CCH], sb1[CCH];
    for (int i = threadIdx.x; i < 128 * CCH; i += blockDim.x) sEmb[i] = emb[i];
    for (int i = threadIdx.x; i < CCH * CCH; i += blockDim.x) { sW0[i] = W0[i]; sW1[i] = W1[i]; }
    if (threadIdx.x < CCH) { sb0[threadIdx.x] = b0[threadIdx.x]; sb1[threadIdx.x] = b1[threadIdx.x]; }
    __syncthreads();

    int i = blockIdx.x * blockDim.x + threadIdx.x;
    if (i >= n) return;
    int zi = z[i];
    float x[CCH], y[CCH];
    #pragma unroll
    for (int c = 0; c < CCH; c++) x[c] = sEmb[zi * CCH + c];
    #pragma unroll
    for (int r = 0; r < CCH; r++) {
        float a = sb0[r];
        #pragma unroll
        for (int c = 0; c < CCH; c++) a += sW0[r * CCH + c] * x[c];
        y[r] = a / (1.f + __expf(-a));               // silu
    }
    float s = 0.f;
    #pragma unroll
    for (int r = 0; r < CCH; r++) {
        float a = sb1[r];
        #pragma unroll
        for (int c = 0; c < CCH; c++) a += sW1[r * CCH + c] * y[c];
        s += a / (1.f + __expf(-a));                 // silu, then channel-sum
    }
    g_s[i] = s;
}

// ---------------------------------------------------------------------------
// Window helper: offsets = {-1,0,1,2} per axis (P=4, arange(P) - (P//2-1))
// ---------------------------------------------------------------------------
__device__ __forceinline__ void window_cell(const float* __restrict__ pos, int i, int t,
                                            float& w, int& idx) {
    const float h = 10.0f / 128.0f;     // exact in fp32
    const float inv = 1.0f / h;
    int a = t >> 4, b = (t >> 2) & 3, c = t & 3;   // x-, y-, z-offset indices
    float px = fmodf(pos[3 * i + 0], 10.0f);
    float py = fmodf(pos[3 * i + 1], 10.0f);
    float pz = fmodf(pos[3 * i + 2], 10.0f);
    int cx = (int)floorf(px / h) + a - 1;
    int cy = (int)floorf(py / h) + b - 1;
    int cz = (int)floorf(pz / h) + c - 1;
    float dx = (px - (float)cx * h) * inv;
    float dy = (py - (float)cy * h) * inv;
    float dz = (pz - (float)cz * h) * inv;
    w = __expf(-0.5f * (dx * dx + dy * dy + dz * dz));
    idx = (((cz & 127) * 128 + (cy & 127)) * 128 + (cx & 127));
}

// 64 threads per particle, 4 particles per 256-thread block
__global__ void k_scatter(const float* __restrict__ pos, int n) {
    int lp = threadIdx.x >> 6;
    int t  = threadIdx.x & 63;
    int i = blockIdx.x * 4 + lp;
    if (i >= n) return;
    float w; int idx;
    window_cell(pos, i, t, w, idx);
    atomicAdd(&g_field0[idx], w * g_s[i]);
}

__global__ void k_gather(const float* __restrict__ pos, float* __restrict__ out, int n) {
    __shared__ float part[8];
    int lp = threadIdx.x >> 6;
    int t  = threadIdx.x & 63;
    int i = blockIdx.x * 4 + lp;
    float v = 0.f;
    if (i < n) {
        float w; int idx;
        window_cell(pos, i, t, w, idx);
        v = w * g_field1[idx];
    }
    #pragma unroll
    for (int o = 16; o; o >>= 1) v += __shfl_xor_sync(0xffffffffu, v, o);
    if ((threadIdx.x & 31) == 0) part[threadIdx.x >> 5] = v;
    __syncthreads();
    if (t == 0 && i < n) out[i] = part[2 * lp] + part[2 * lp + 1];
}

// ---------------------------------------------------------------------------
// Separable circular conv along z or y. Block: 32-wide x-chunk (contiguous),
// full 128 along the conv axis, fixed "other" coord. 16 KB smem tile.
//   z-pass: astride = 128*128, ostride = 128,        dir=0: field0 -> field1
//   y-pass: astride = 128,     ostride = 128*128,    dir=1: field1 -> field0
// ---------------------------------------------------------------------------
__global__ void k_conv(int astride, int ostride, int dir, Taps tp) {
    const float* __restrict__ in = dir ? g_field1 : g_field0;
    float* __restrict__ out      = dir ? g_field0 : g_field1;
    __shared__ float tile[NGRID][32];
    int tx = threadIdx.x & 31;
    int tz = threadIdx.x >> 5;            // 0..7
    int x0 = blockIdx.x * 32;
    int other = blockIdx.y;
    const float* base = in + other * ostride + x0 + tx;
    #pragma unroll
    for (int zz = tz; zz < NGRID; zz += 8)
        tile[zz][tx] = base[zz * astride];
    __syncthreads();
    float* ob = out + other * ostride + x0 + tx;
    #pragma unroll
    for (int zz = tz; zz < NGRID; zz += 8) {
        float acc = tp.t[0] * tile[zz][tx];
        #pragma unroll
        for (int d = 1; d <= RAD; d++)
            acc += tp.t[d] * (tile[(zz + d) & 127][tx] + tile[(zz - d) & 127][tx]);
        ob[zz * astride] = acc;
    }
}

// x-axis pass (lines are contiguous). 8 lines per 256-thread block. field0->field1.
__global__ void k_conv_x(Taps tp) {
    __shared__ float tile[8][NGRID];
    int lx = threadIdx.x & 31;
    int ln = threadIdx.x >> 5;            // 0..7
    int line = blockIdx.x * 8 + ln;
    const float* base = g_field0 + line * NGRID;
    #pragma unroll
    for (int k = 0; k < 4; k++) tile[ln][lx + 32 * k] = base[lx + 32 * k];
    __syncthreads();
    float* ob = g_field1 + line * NGRID;
    #pragma unroll
    for (int k = 0; k < 4; k++) {
        int xx = lx + 32 * k;
        float acc = tp.t[0] * tile[ln][xx];
        #pragma unroll
        for (int d = 1; d <= RAD; d++)
            acc += tp.t[d] * (tile[ln][(xx + d) & 127] + tile[ln][(xx - d) & 127]);
        ob[xx] = acc;
    }
}

// ---------------------------------------------------------------------------
// Host-side exact taps: inverse DFT of exp(-0.5*sig^2*k^2) with sig = h = L/NG.
// k(d) = (1/128)[ g(0) + 2*sum_{m=1..63} g(m) cos(pi m d/64) + g(64) cos(pi d) ]
// ---------------------------------------------------------------------------
static Taps make_taps() {
    Taps tp;
    for (int d = 0; d <= RAD; d++) {
        double acc = 1.0;  // m = 0
        for (int m = 1; m < 64; m++) {
            double a = M_PI * (double)m / 64.0;
            acc += 2.0 * exp(-0.5 * a * a) * cos(M_PI * (double)(m * d) / 64.0);
        }
        acc += exp(-0.5 * M_PI * M_PI) * cos(M_PI * (double)d);  // m = 64 (Nyquist)
        tp.t[d] = (float)(acc / 128.0);
    }
    return tp;
}

extern "C" void kernel_launch(void* const* d_in, const int* in_sizes, int n_in,
                              void* d_out, int out_size) {
    const int*   z   = (const int*)  d_in[0];
    const float* pos = (const float*)d_in[1];
    // d_in[2] = batch (all zeros, NBATCH=1) — unused
    const float* emb = (const float*)d_in[3];
    const float* W0  = (const float*)d_in[4];
    const float* b0  = (const float*)d_in[5];
    const float* W1  = (const float*)d_in[6];
    const float* b1  = (const float*)d_in[7];
    float* out = (float*)d_out;
    int n = in_sizes[0];

    Taps tp = make_taps();   // host double math; baked into the captured graph

    k_zero<<<NG3 / 4 / 256, 256>>>();
    k_mlp<<<(n + 127) / 128, 128>>>(z, emb, W0, b0, W1, b1, n);
    k_scatter<<<(n + 3) / 4, 256>>>(pos, n);
    k_conv<<<dim3(4, 128), 256>>>(NGRID * NGRID, NGRID, 0, tp);  // z-axis: f0 -> f1
    k_conv<<<dim3(4, 128), 256>>>(NGRID, NGRID * NGRID, 1, tp);  // y-axis: f1 -> f0
    k_conv_x<<<NGRID * NGRID / 8, 256>>>(tp);                    // x-axis: f0 -> f1
    k_gather<<<(n + 3) / 4, 256>>>(pos, out, n);
}